// round 7
// baseline (speedup 1.0000x reference)
#include <cuda_runtime.h>
#include <float.h>

#define IN_DIM 256
#define OUT_DIM 512
#define MEM_LEN 131072
#define TOPK 16

#define ENC_PARTS 64
#define ROWS_PER_PART (IN_DIM / ENC_PARTS)   // 4

#define DIST_BLOCKS 608                       // 152 SMs * 4 blocks
#define DIST_NT 512                           // 16 warps
#define NWARPS (DIST_BLOCKS * (DIST_NT / 32)) // 9728 warps
#define ROWS_BASE (MEM_LEN / NWARPS)          // 13
#define ROWS_REM  (MEM_LEN % NWARPS)          // 4608 warps do 14

#define CAND_LISTS DIST_BLOCKS                // 608 sorted 16-lists
#define CAND_N (CAND_LISTS * TOPK)

__device__ float g_enc[OUT_DIM];
__device__ float g_part[ENC_PARTS * OUT_DIM];
__device__ float g_cand[CAND_N];
__device__ unsigned int g_ctr_enc;
__device__ unsigned int g_ctr_dist;

// ---------------------------------------------------------------------------
// bitonic clean of a register-resident 16-array (bitonic -> sorted ascending)
// ---------------------------------------------------------------------------
__device__ __forceinline__ void bitonic_clean16(float* r) {
#pragma unroll
    for (int j = 8; j > 0; j >>= 1) {
#pragma unroll
        for (int i = 0; i < TOPK; ++i) {
            if ((i & j) == 0 && (i ^ j) > i) {
                float lo = fminf(r[i], r[i ^ j]);
                float hi = fmaxf(r[i], r[i ^ j]);
                r[i] = lo; r[i ^ j] = hi;
            }
        }
    }
}

// merge own sorted-16 with register list b (sorted): keep 16 smallest, sorted
__device__ __forceinline__ void reg_merge16(float* r, const float* b) {
#pragma unroll
    for (int i = 0; i < TOPK; ++i) r[i] = fminf(r[i], b[TOPK - 1 - i]);
    bitonic_clean16(r);
}

// merge own sorted-16 with XOR-partner lane's sorted-16; all lanes end with
// the sorted 16 smallest of the union. Branchless.
__device__ __forceinline__ void shfl_merge16(float* r, int off) {
#pragma unroll
    for (int i = 0; i < 8; ++i) {
        float ohi = __shfl_xor_sync(0xFFFFFFFFu, r[15 - i], off);
        float olo = __shfl_xor_sync(0xFFFFFFFFu, r[i], off);
        r[i]      = fminf(r[i], ohi);
        r[15 - i] = fminf(r[15 - i], olo);
    }
    bitonic_clean16(r);
}

// ---------------------------------------------------------------------------
// Kernel 1: fused GEMV. 64 blocks x 512 threads; last block finishes.
// ---------------------------------------------------------------------------
__global__ void enc_kernel(const float* __restrict__ data,
                           const float* __restrict__ mean,
                           const float* __restrict__ stdv,
                           const float* __restrict__ W,
                           const float* __restrict__ b) {
    __shared__ float xn[ROWS_PER_PART];
    __shared__ unsigned int s_ticket;

    int t = threadIdx.x;              // output column
    int r0 = blockIdx.x * ROWS_PER_PART;
    if (t < ROWS_PER_PART) {
        int r = r0 + t;
        float s = stdv[r];
        xn[t] = (s == 0.0f) ? 0.0f : (data[r] - mean[r]) / s;
    }
    __syncthreads();
    float acc = 0.0f;
#pragma unroll
    for (int i = 0; i < ROWS_PER_PART; ++i)
        acc = fmaf(xn[i], W[(size_t)(r0 + i) * OUT_DIM + t], acc);
    g_part[blockIdx.x * OUT_DIM + t] = acc;

    __threadfence();
    __syncthreads();
    if (t == 0) s_ticket = atomicAdd(&g_ctr_enc, 1u);
    __syncthreads();
    if (s_ticket == ENC_PARTS - 1) {
        __threadfence();
        float sum = b[t];
#pragma unroll
        for (int p = 0; p < ENC_PARTS; ++p)
            sum += g_part[p * OUT_DIM + t];
        g_enc[t] = tanhf(sum);
        __threadfence();
        __syncthreads();
        if (t == 0) g_ctr_enc = 0u;
    }
}

// ---------------------------------------------------------------------------
// Kernel 2: dist via per-warp grid-stride rows + warp top-16 + block merge
// + last-block global merge & loss. 608 blocks x 512 thr, <=32 regs.
// ---------------------------------------------------------------------------
__global__ void __launch_bounds__(DIST_NT, 4)
dist_topk_kernel(const float* __restrict__ memory,
                 const float* __restrict__ exp_w,
                 float* __restrict__ out) {
    __shared__ float se[OUT_DIM];
    __shared__ float swarp[16 * TOPK];
    __shared__ unsigned int s_ticket;

    int t = threadIdx.x;
    se[t] = g_enc[t];
    __syncthreads();

    int warp = t >> 5;
    int lane = t & 31;
    int gw   = blockIdx.x * 16 + warp;        // global warp id, 0..9727
    int nrows = ROWS_BASE + (gw < ROWS_REM ? 1 : 0);   // 13 or 14

    const float4* es = (const float4*)se;
    float my = FLT_MAX;   // lane k holds dist of this warp's k-th row

    for (int k = 0; k < nrows; ++k) {
        size_t row = (size_t)gw + (size_t)k * NWARPS;
        const float4* m = (const float4*)(memory + row * OUT_DIM);
        float4 v0 = __ldg(&m[0 * 32 + lane]);
        float4 v1 = __ldg(&m[1 * 32 + lane]);
        float4 v2 = __ldg(&m[2 * 32 + lane]);
        float4 v3 = __ldg(&m[3 * 32 + lane]);

        float4 e0 = es[0 * 32 + lane];
        float4 e1 = es[1 * 32 + lane];
        float4 e2 = es[2 * 32 + lane];
        float4 e3 = es[3 * 32 + lane];

        float s = 0.0f;
        s += fabsf(v0.x - e0.x) + fabsf(v0.y - e0.y) + fabsf(v0.z - e0.z) + fabsf(v0.w - e0.w);
        s += fabsf(v1.x - e1.x) + fabsf(v1.y - e1.y) + fabsf(v1.z - e1.z) + fabsf(v1.w - e1.w);
        s += fabsf(v2.x - e2.x) + fabsf(v2.y - e2.y) + fabsf(v2.z - e2.z) + fabsf(v2.w - e2.w);
        s += fabsf(v3.x - e3.x) + fabsf(v3.y - e3.y) + fabsf(v3.z - e3.z) + fabsf(v3.w - e3.w);

#pragma unroll
        for (int o = 16; o > 0; o >>= 1)
            s += __shfl_xor_sync(0xFFFFFFFFu, s, o);

        my = (lane == k) ? s : my;
    }

    // warp bitonic sort over 32 lane values (valid + FLT_MAX pad), ascending
#pragma unroll
    for (int k = 2; k <= 32; k <<= 1) {
#pragma unroll
        for (int j = k >> 1; j > 0; j >>= 1) {
            float other = __shfl_xor_sync(0xFFFFFFFFu, my, j);
            bool up = ((lane & k) == 0);
            bool lower = ((lane & j) == 0);
            my = (lower == up) ? fminf(my, other) : fmaxf(my, other);
        }
    }
    if (lane < TOPK) swarp[warp * TOPK + lane] = my;
    __syncthreads();

    // warp 0 merges the 16 per-warp lists -> block's sorted top-16
    if (warp == 0) {
        float r[TOPK];
#pragma unroll
        for (int i = 0; i < TOPK; ++i)
            r[i] = (lane < 16) ? swarp[lane * TOPK + i] : FLT_MAX;
        shfl_merge16(r, 16);
        shfl_merge16(r, 8);
        shfl_merge16(r, 4);
        shfl_merge16(r, 2);
        shfl_merge16(r, 1);
        if (lane == 0) {
            float4* o4 = (float4*)(g_cand + blockIdx.x * TOPK);
            o4[0] = make_float4(r[0], r[1], r[2], r[3]);
            o4[1] = make_float4(r[4], r[5], r[6], r[7]);
            o4[2] = make_float4(r[8], r[9], r[10], r[11]);
            o4[3] = make_float4(r[12], r[13], r[14], r[15]);
        }
    }

    // ---- last-block-done: merge 608 sorted 16-lists + loss ----
    __threadfence();
    __syncthreads();
    if (t == 0) s_ticket = atomicAdd(&g_ctr_dist, 1u);
    __syncthreads();
    if (s_ticket != DIST_BLOCKS - 1) return;
    __threadfence();

    float r[TOPK];
    {
        const float4* c4 = (const float4*)(g_cand + t * TOPK);
        float4 a = c4[0], bq = c4[1], c = c4[2], d = c4[3];
        r[0]=a.x;  r[1]=a.y;  r[2]=a.z;  r[3]=a.w;
        r[4]=bq.x; r[5]=bq.y; r[6]=bq.z; r[7]=bq.w;
        r[8]=c.x;  r[9]=c.y;  r[10]=c.z; r[11]=c.w;
        r[12]=d.x; r[13]=d.y; r[14]=d.z; r[15]=d.w;
    }
    // fold lists 512..607 into threads 0..95
    if (t < CAND_LISTS - DIST_NT) {
        float b2[TOPK];
        const float4* c4 = (const float4*)(g_cand + (DIST_NT + t) * TOPK);
        float4 a = c4[0], bq = c4[1], c = c4[2], d = c4[3];
        b2[0]=a.x;  b2[1]=a.y;  b2[2]=a.z;  b2[3]=a.w;
        b2[4]=bq.x; b2[5]=bq.y; b2[6]=bq.z; b2[7]=bq.w;
        b2[8]=c.x;  b2[9]=c.y;  b2[10]=c.z; b2[11]=c.w;
        b2[12]=d.x; b2[13]=d.y; b2[14]=d.z; b2[15]=d.w;
        reg_merge16(r, b2);
    }

    // in-warp 32 -> 1, then 16 warp lists -> 1
    shfl_merge16(r, 16);
    shfl_merge16(r, 8);
    shfl_merge16(r, 4);
    shfl_merge16(r, 2);
    shfl_merge16(r, 1);
    if (lane == 0) {
#pragma unroll
        for (int i = 0; i < TOPK; ++i) swarp[warp * TOPK + i] = r[i];
    }
    __syncthreads();
    if (warp == 0) {
#pragma unroll
        for (int i = 0; i < TOPK; ++i)
            r[i] = (lane < 16) ? swarp[lane * TOPK + i] : FLT_MAX;
        shfl_merge16(r, 16);
        shfl_merge16(r, 8);
        shfl_merge16(r, 4);
        shfl_merge16(r, 2);
        shfl_merge16(r, 1);
        if (lane == 0) {
            float num = 0.0f, den = 0.0f;
#pragma unroll
            for (int i = 0; i < TOPK; ++i) {
                float w = exp_w[i];
                num = fmaf(r[i], w, num);
                den += w;
            }
            out[0] = num / den;
            g_ctr_dist = 0u;
        }
    }
}

// ---------------------------------------------------------------------------
// Launch.
// Inputs: data[256], mean[256], std[256], memory[131072*512],
//         W[256*512], b[512], exp_w[16]  ->  out[1] float
// ---------------------------------------------------------------------------
extern "C" void kernel_launch(void* const* d_in, const int* in_sizes, int n_in,
                              void* d_out, int out_size) {
    const float* data   = (const float*)d_in[0];
    const float* mean   = (const float*)d_in[1];
    const float* stdv   = (const float*)d_in[2];
    const float* memory = (const float*)d_in[3];
    const float* W      = (const float*)d_in[4];
    const float* b      = (const float*)d_in[5];
    const float* exp_w  = (const float*)d_in[6];
    float* out = (float*)d_out;

    enc_kernel<<<ENC_PARTS, OUT_DIM>>>(data, mean, stdv, W, b);
    dist_topk_kernel<<<DIST_BLOCKS, DIST_NT>>>(memory, exp_w, out);
}